// round 2
// baseline (speedup 1.0000x reference)
#include <cuda_runtime.h>

// KMeansProbSampler: 8 iterations of weighted k-means scatter on a 1024x1024
// heatmap with 128 clusters.
//
// Restructure: d2(pixel,k) = base_k(row) - 2*c*cc_k + (r^2+c^2)
//   base_k(row) = cr_k^2 + cc_k^2 - 2*row*cr_k   (precomputed per block/row)
// The (r^2+c^2) shift is common to all clusters -> argmin unaffected.
// 4 consecutive pixels per thread: key(c+1) = key(c) + (-2*cc_k)  -> FADD chain.
// Pass 1: chunk minima only (FMNMX). Pass 2: locate chunk by exact equality,
// rescan 16 clusters with strict '<' ascending (first-index ties). Exact d2
// recomputed for the winner only (precision for the 1/max(1,sqrt(d2)) weight).

#define HH 1024
#define WW 1024
#define CC 128
#define NITER 8
#define PX 4
#define TPB 256
#define NCHUNK 8
#define CHSZ 16

__device__ float g_bufA[CC * 2];
__device__ float g_bufB[CC * 2];

__global__ void zero256_kernel(float* t) {
    t[threadIdx.x] = 0.0f;
}

__global__ __launch_bounds__(TPB) void kmeans_iter_kernel(
    const float* __restrict__ clusters,   // [C,2] current positions (row, col)
    const float* __restrict__ heat,       // [H,W]
    float* __restrict__ target)           // [C,2] output sums (pre-zeroed)
{
    __shared__ float2 sh_bs[CC];   // (base_k(row), -2*cc_k)
    __shared__ float2 sh_cl[CC];   // (cr_k, cc_k)
    __shared__ float  sacc[CC * 2];

    const int   row = blockIdx.x;          // one block per image row
    const float rf  = (float)row;
    const int   t   = threadIdx.x;

    if (t < CC) {
        float cr = clusters[2 * t];
        float cc = clusters[2 * t + 1];
        float n    = fmaf(cc, cc, cr * cr);
        float base = fmaf(-2.0f * cr, rf, n);
        sh_bs[t] = make_float2(base, -2.0f * cc);
        sh_cl[t] = make_float2(cr, cc);
    }
    sacc[t] = 0.0f;   // TPB == CC*2
    __syncthreads();

    const int   c0  = t * PX;
    const float c0f = (float)c0;

    float4 hv = *reinterpret_cast<const float4*>(heat + row * WW + c0);
    float heats[PX] = {hv.x, hv.y, hv.z, hv.w};

    // ---- pass 1: chunk minima of shifted-d2 keys ----
    float m[NCHUNK][PX];
#pragma unroll
    for (int ch = 0; ch < NCHUNK; ch++)
#pragma unroll
        for (int j = 0; j < PX; j++) m[ch][j] = 3.4e38f;

#pragma unroll
    for (int ch = 0; ch < NCHUNK; ch++) {
#pragma unroll
        for (int q = 0; q < CHSZ; q++) {
            float2 bs = sh_bs[ch * CHSZ + q];
            float k0 = fmaf(c0f, bs.y, bs.x);
            float k1 = k0 + bs.y;
            float k2 = k1 + bs.y;
            float k3 = k2 + bs.y;
            m[ch][0] = fminf(m[ch][0], k0);
            m[ch][1] = fminf(m[ch][1], k1);
            m[ch][2] = fminf(m[ch][2], k2);
            m[ch][3] = fminf(m[ch][3], k3);
        }
    }

    // ---- pass 2 + epilogue, per pixel ----
#pragma unroll
    for (int j = 0; j < PX; j++) {
        float gm = m[0][j];
#pragma unroll
        for (int ch = 1; ch < NCHUNK; ch++) gm = fminf(gm, m[ch][j]);

        // chunk holding the min: descending scan -> lowest matching chunk.
        // gm is bitwise one of the m[ch][j] values, so '==' is safe.
        int bch = 0;
#pragma unroll
        for (int ch = NCHUNK - 1; ch >= 0; ch--)
            if (m[ch][j] == gm) bch = ch;

        // rescan the 16 clusters of that chunk; ascending, strict '<'
        // -> first (lowest) index wins on ties, matching argmin.
        float bm   = 3.4e38f;
        int   best = bch * CHSZ;
        for (int q = 0; q < CHSZ; q++) {
            float2 bs  = sh_bs[bch * CHSZ + q];
            float  key = fmaf(c0f, bs.y, bs.x);
#pragma unroll
            for (int jj = 0; jj < j; jj++) key += bs.y;
            if (key < bm) { bm = key; best = bch * CHSZ + q; }
        }

        // exact d2 for the winner (avoids the expansion's cancellation error)
        float2 cl = sh_cl[best];
        float  cf = c0f + (float)j;
        float  dr = rf - cl.x;
        float  dc = cf - cl.y;
        float  d2   = fmaf(dr, dr, dc * dc);
        float  dist = fmaxf(1.0f, sqrtf(d2));
        float  w    = heats[j] / dist;
        atomicAdd(&sacc[2 * best],     w * rf);
        atomicAdd(&sacc[2 * best + 1], w * cf);
    }

    __syncthreads();
    atomicAdd(&target[t], sacc[t]);
}

extern "C" void kernel_launch(void* const* d_in, const int* in_sizes, int n_in,
                              void* d_out, int out_size)
{
    const float* clusters = (const float*)d_in[0];
    const float* heat     = (const float*)d_in[1];
    if (in_sizes[0] != CC * 2) {  // robustness to metadata order
        const float* tmp = clusters; clusters = heat; heat = tmp;
    }

    float* bufA = nullptr;
    float* bufB = nullptr;
    cudaGetSymbolAddress((void**)&bufA, g_bufA);
    cudaGetSymbolAddress((void**)&bufB, g_bufB);
    float* out = (float*)d_out;

    const float* cur = clusters;
    for (int it = 0; it < NITER; it++) {
        float* target;
        if (it == NITER - 1)      target = out;
        else if ((it & 1) == 0)   target = bufA;
        else                      target = bufB;

        zero256_kernel<<<1, CC * 2>>>(target);
        kmeans_iter_kernel<<<HH, TPB>>>(cur, heat, target);
        cur = target;
    }
}

// round 4
// speedup vs baseline: 2.1495x; 2.1495x over previous
#include <cuda_runtime.h>

// KMeansProbSampler: 8 iterations of weighted k-means scatter on a 1024x1024
// heatmap with 128 clusters.
//
// R3 structure:
//  - Per-iteration prep kernel writes (n, -2cr, -2cc) + (cr, cc) per cluster
//    into a __device__ mirror; a 3KB D2D memcpyAsync moves it into __constant__
//    memory. Pass-1 then reads cluster data via LDCU (uniform-const port),
//    taking the hot loop completely off the L1TEX/LSU path (was 67% of peak).
//  - key_j(pixel, k) = fmaf(c_j, -2cc_k, base2_k), base2_k = fmaf(r, -2cr_k, n_k)
//    (shifted squared distance; the (r^2+c^2) shift is argmin-invariant).
//    4 independent FFMAs per cluster (no serial FADD chain).
//  - Pass 1 tracks only chunk minima (8 chunks x 16 clusters, FMNMX).
//  - Pass 2 locates the chunk by exact equality (fminf returns one of its args
//    bitwise), then rescans 16 clusters from shared via LDS.128 with strict '<'
//    ascending (first-index ties, matching argmin).
//  - Exact d2 recomputed for the winner only; w = h * min(1, rsqrt(d2)).
//  - Epilogue run-combines same-cluster pixels before shared atomicAdd.

#define HH 1024
#define WW 1024
#define CC 128
#define NITER 8
#define PX 4
#define TPB 256
#define NCHUNK 8
#define CHSZ 16

struct CData {
    float4 key[CC];   // (n, -2cr, -2cc, 0)
    float2 pos[CC];   // (cr, cc)
};

__constant__ CData c_data;
__device__   CData g_data;

__device__ float g_bufA[CC * 2];
__device__ float g_bufB[CC * 2];

// prep: build cluster constants from current positions + zero the target sums
__global__ void prep_kernel(const float* __restrict__ clusters,
                            float* __restrict__ target)
{
    int t = threadIdx.x;
    if (t < CC) {
        float cr = clusters[2 * t];
        float cc = clusters[2 * t + 1];
        float n  = fmaf(cr, cr, cc * cc);
        g_data.key[t] = make_float4(n, -2.0f * cr, -2.0f * cc, 0.0f);
        g_data.pos[t] = make_float2(cr, cc);
    }
    target[t] = 0.0f;   // TPB == CC*2
}

__global__ __launch_bounds__(TPB) void kmeans_iter_kernel(
    const float* __restrict__ heat,       // [H,W]
    float* __restrict__ target)           // [C,2] output sums (pre-zeroed)
{
    __shared__ __align__(16) float2 sh_kb[CC];   // (base2_k, -2cc_k)
    __shared__ float2 sh_pos[CC];                // (cr_k, cc_k)
    __shared__ float  sacc[CC * 2];

    const int   row = blockIdx.x;
    const float rf  = (float)row;
    const int   t   = threadIdx.x;

    if (t < CC) {
        float4 k = c_data.key[t];
        float  base2 = fmaf(rf, k.y, k.x);       // must match pass-1 expression
        sh_kb[t]  = make_float2(base2, k.z);
        sh_pos[t] = c_data.pos[t];
    }
    sacc[t] = 0.0f;
    __syncthreads();

    const int   c0  = t * PX;
    const float c0f = (float)c0;
    const float cf1 = c0f + 1.0f, cf2 = c0f + 2.0f, cf3 = c0f + 3.0f;

    float4 hv = *reinterpret_cast<const float4*>(heat + row * WW + c0);
    float heats[PX] = {hv.x, hv.y, hv.z, hv.w};
    float cfs[PX]   = {c0f, cf1, cf2, cf3};

    // ---- pass 1: chunk minima of shifted-d2 keys (constants via LDCU) ----
    float m[NCHUNK][PX];
#pragma unroll
    for (int ch = 0; ch < NCHUNK; ch++)
#pragma unroll
        for (int j = 0; j < PX; j++) m[ch][j] = 3.4e38f;

#pragma unroll
    for (int ch = 0; ch < NCHUNK; ch++) {
#pragma unroll
        for (int q = 0; q < CHSZ; q++) {
            float4 k  = c_data.key[ch * CHSZ + q];
            float  b2 = fmaf(rf, k.y, k.x);
            float  k0 = fmaf(c0f, k.z, b2);
            float  k1 = fmaf(cf1, k.z, b2);
            float  k2 = fmaf(cf2, k.z, b2);
            float  k3 = fmaf(cf3, k.z, b2);
            m[ch][0] = fminf(m[ch][0], k0);
            m[ch][1] = fminf(m[ch][1], k1);
            m[ch][2] = fminf(m[ch][2], k2);
            m[ch][3] = fminf(m[ch][3], k3);
        }
    }

    // ---- pass 2 + epilogue, per pixel, with atomic run-combining ----
    int   curBest = -1;
    float ws = 0.0f, wc = 0.0f;

#pragma unroll
    for (int j = 0; j < PX; j++) {
        const float cj = cfs[j];

        float gm = m[0][j];
#pragma unroll
        for (int ch = 1; ch < NCHUNK; ch++) gm = fminf(gm, m[ch][j]);

        // chunk holding the min: descending equality scan -> lowest chunk.
        int bch = 0;
#pragma unroll
        for (int ch = NCHUNK - 1; ch >= 0; ch--)
            if (m[ch][j] == gm) bch = ch;

        // rescan 16 clusters of that chunk (2 per LDS.128), ascending strict '<'
        const float4* kb4 = reinterpret_cast<const float4*>(sh_kb) + bch * (CHSZ / 2);
        float bm   = 3.4e38f;
        int   best = bch * CHSZ;
#pragma unroll
        for (int q2 = 0; q2 < CHSZ / 2; q2++) {
            float4 kk = kb4[q2];
            float  ka = fmaf(cj, kk.y, kk.x);
            float  kb = fmaf(cj, kk.w, kk.z);
            if (ka < bm) { bm = ka; best = bch * CHSZ + 2 * q2; }
            if (kb < bm) { bm = kb; best = bch * CHSZ + 2 * q2 + 1; }
        }

        // exact d2 for the winner; w = h * min(1, rsqrt(d2))
        float2 p  = sh_pos[best];
        float  dr = rf - p.x;
        float  dc = cj - p.y;
        float  d2 = fmaf(dr, dr, dc * dc);
        float  w  = heats[j] * fminf(1.0f, rsqrtf(d2));

        if (best == curBest) {
            ws += w;
            wc  = fmaf(w, cj, wc);
        } else {
            if (curBest >= 0) {
                atomicAdd(&sacc[2 * curBest],     ws * rf);
                atomicAdd(&sacc[2 * curBest + 1], wc);
            }
            curBest = best;
            ws = w;
            wc = w * cj;
        }
    }
    atomicAdd(&sacc[2 * curBest],     ws * rf);
    atomicAdd(&sacc[2 * curBest + 1], wc);

    __syncthreads();
    atomicAdd(&target[t], sacc[t]);
}

extern "C" void kernel_launch(void* const* d_in, const int* in_sizes, int n_in,
                              void* d_out, int out_size)
{
    const float* clusters = (const float*)d_in[0];
    const float* heat     = (const float*)d_in[1];
    if (in_sizes[0] != CC * 2) {  // robustness to metadata order
        const float* tmp = clusters; clusters = heat; heat = tmp;
    }

    float* bufA = nullptr;
    float* bufB = nullptr;
    void*  cSym = nullptr;
    void*  gSym = nullptr;
    cudaGetSymbolAddress((void**)&bufA, g_bufA);
    cudaGetSymbolAddress((void**)&bufB, g_bufB);
    cudaGetSymbolAddress(&cSym, c_data);
    cudaGetSymbolAddress(&gSym, g_data);
    float* out = (float*)d_out;

    const float* cur = clusters;
    for (int it = 0; it < NITER; it++) {
        float* target;
        if (it == NITER - 1)      target = out;
        else if ((it & 1) == 0)   target = bufA;
        else                      target = bufB;

        prep_kernel<<<1, CC * 2>>>(cur, target);
        cudaMemcpyAsync(cSym, gSym, sizeof(CData), cudaMemcpyDeviceToDevice);
        kmeans_iter_kernel<<<HH, TPB>>>(heat, target);
        cur = target;
    }
}

// round 6
// speedup vs baseline: 2.4887x; 1.1578x over previous
#include <cuda_runtime.h>

// KMeansProbSampler: 8 iterations of weighted k-means scatter on a 1024x1024
// heatmap with 128 clusters.
//
// R5: warp-span line pruning.
//   key_k(c) = b2_k + c*s_k   (shifted squared distance; linear in c;
//                              the (r^2+c^2) shift is argmin-invariant)
//   b2_k = fmaf(row, -2*cr_k, cr_k^2+cc_k^2),  s_k = -2*cc_k
// Per warp (128 consecutive pixels of one row):
//   - evaluate each cluster's key at span endpoints (fma of a monotone linear
//     function is weakly monotone -> endpoint values bound the span),
//   - UB = min_k max(keyLo,keyHi)  (upper bound on pixel-min over the span),
//   - keep cluster k iff min(keyLo,keyHi) <= UB  (winner & ties always kept),
//   - ballot-compact survivors (ascending cluster index) into shared,
//   - each pixel scans only survivors with strict '<' (first = lowest index,
//     matching argmin tie semantics).
// Exact d2 recomputed for the winner only; w = h * min(1, rsqrt(d2)).
// Epilogue run-combines same-cluster pixels before shared atomicAdd.

#define HH 1024
#define WW 1024
#define CC 128
#define NITER 8
#define PX 4
#define TPB 256
#define NWARP (TPB / 32)
#define WSPAN (32 * PX)      // pixels per warp

__device__ float g_bufA[CC * 2];
__device__ float g_bufB[CC * 2];

__global__ void zero_kernel(float* t) {
    t[threadIdx.x] = 0.0f;
}

__global__ __launch_bounds__(TPB) void kmeans_iter_kernel(
    const float* __restrict__ clusters,   // [C,2] (row, col)
    const float* __restrict__ heat,       // [H,W]
    float* __restrict__ target)           // [C,2] output sums (pre-zeroed)
{
    __shared__ float2 sh_line[CC];              // (b2_k, s_k)
    __shared__ float2 sh_pos[CC];               // (cr_k, cc_k)
    __shared__ float2 sh_surv[NWARP][CC];       // compacted (b2, s) per warp
    __shared__ short  sh_sidx[NWARP][CC];       // original cluster index
    __shared__ float  sacc[CC * 2];

    const int   row  = blockIdx.x;
    const float rf   = (float)row;
    const int   t    = threadIdx.x;
    const int   w    = t >> 5;
    const int   lane = t & 31;

    if (t < CC) {
        float cr = clusters[2 * t];
        float cc = clusters[2 * t + 1];
        float n  = fmaf(cr, cr, cc * cc);
        sh_line[t] = make_float2(fmaf(rf, -2.0f * cr, n), -2.0f * cc);
        sh_pos[t]  = make_float2(cr, cc);
    }
    sacc[t] = 0.0f;
    __syncthreads();

    // ---- warp-span pruning ----
    const float cLo = (float)(w * WSPAN);
    const float cHi = (float)(w * WSPAN + WSPAN - 1);

    float  mn[4], mx[4];
    float2 ln[4];
#pragma unroll
    for (int q = 0; q < 4; q++) {
        float2 L   = sh_line[lane + 32 * q];
        float  kLo = fmaf(cLo, L.y, L.x);
        float  kHi = fmaf(cHi, L.y, L.x);
        mn[q] = fminf(kLo, kHi);
        mx[q] = fmaxf(kLo, kHi);
        ln[q] = L;
    }
    float ub = fminf(fminf(mx[0], mx[1]), fminf(mx[2], mx[3]));
#pragma unroll
    for (int off = 16; off; off >>= 1)
        ub = fminf(ub, __shfl_xor_sync(0xffffffffu, ub, off));

    int base = 0;
#pragma unroll
    for (int q = 0; q < 4; q++) {                 // ascending q, ascending lane
        bool     p   = (mn[q] <= ub);             // non-strict: ties survive
        unsigned bal = __ballot_sync(0xffffffffu, p);
        int      pos = base + __popc(bal & ((1u << lane) - 1u));
        if (p) {
            sh_surv[w][pos] = ln[q];
            sh_sidx[w][pos] = (short)(lane + 32 * q);
        }
        base += __popc(bal);
    }
    const int nsurv = base;
    __syncwarp();

    // ---- per-pixel scan over survivors ----
    const int   c0  = t * PX;
    const float c0f = (float)c0;
    const float cfs[PX]   = {c0f, c0f + 1.0f, c0f + 2.0f, c0f + 3.0f};
    float4 hv = *reinterpret_cast<const float4*>(heat + row * WW + c0);
    const float heats[PX] = {hv.x, hv.y, hv.z, hv.w};

    float bm0 = 3.4e38f, bm1 = 3.4e38f, bm2 = 3.4e38f, bm3 = 3.4e38f;
    int   bi0 = 0, bi1 = 0, bi2 = 0, bi3 = 0;
    for (int i = 0; i < nsurv; i++) {
        float2 L  = sh_surv[w][i];
        float  k0 = fmaf(cfs[0], L.y, L.x);
        float  k1 = fmaf(cfs[1], L.y, L.x);
        float  k2 = fmaf(cfs[2], L.y, L.x);
        float  k3 = fmaf(cfs[3], L.y, L.x);
        if (k0 < bm0) { bm0 = k0; bi0 = i; }     // strict '<': lowest index wins
        if (k1 < bm1) { bm1 = k1; bi1 = i; }
        if (k2 < bm2) { bm2 = k2; bi2 = i; }
        if (k3 < bm3) { bm3 = k3; bi3 = i; }
    }
    int bests[PX] = { sh_sidx[w][bi0], sh_sidx[w][bi1],
                      sh_sidx[w][bi2], sh_sidx[w][bi3] };

    // ---- epilogue: exact d2 for winners, run-combined shared atomics ----
    int   curBest = -1;
    float ws = 0.0f, wc = 0.0f;
#pragma unroll
    for (int j = 0; j < PX; j++) {
        int    best = bests[j];
        float2 p    = sh_pos[best];
        float  dr   = rf - p.x;
        float  dc   = cfs[j] - p.y;
        float  d2   = fmaf(dr, dr, dc * dc);
        float  wgt  = heats[j] * fminf(1.0f, rsqrtf(d2));

        if (best == curBest) {
            ws += wgt;
            wc  = fmaf(wgt, cfs[j], wc);
        } else {
            if (curBest >= 0) {
                atomicAdd(&sacc[2 * curBest],     ws * rf);
                atomicAdd(&sacc[2 * curBest + 1], wc);
            }
            curBest = best;
            ws = wgt;
            wc = wgt * cfs[j];
        }
    }
    atomicAdd(&sacc[2 * curBest],     ws * rf);
    atomicAdd(&sacc[2 * curBest + 1], wc);

    __syncthreads();
    atomicAdd(&target[t], sacc[t]);
}

extern "C" void kernel_launch(void* const* d_in, const int* in_sizes, int n_in,
                              void* d_out, int out_size)
{
    const float* clusters = (const float*)d_in[0];
    const float* heat     = (const float*)d_in[1];
    if (in_sizes[0] != CC * 2) {  // robustness to metadata order
        const float* tmp = clusters; clusters = heat; heat = tmp;
    }

    float* bufA = nullptr;
    float* bufB = nullptr;
    cudaGetSymbolAddress((void**)&bufA, g_bufA);
    cudaGetSymbolAddress((void**)&bufB, g_bufB);
    float* out = (float*)d_out;

    const float* cur = clusters;
    for (int it = 0; it < NITER; it++) {
        float* target;
        if (it == NITER - 1)      target = out;
        else if ((it & 1) == 0)   target = bufA;
        else                      target = bufB;

        zero_kernel<<<1, CC * 2>>>(target);
        kmeans_iter_kernel<<<HH, TPB>>>(cur, heat, target);
        cur = target;
    }
}